// round 5
// baseline (speedup 1.0000x reference)
#include <cuda_runtime.h>
#include <cstddef>

// 2-layer LSTM (H=20) + FC head, B=4096, T=512, D=1.
// 8 lanes per sequence: lanes 0-3 own (I,F) gate-pairs for 5 units each,
// lanes 4-7 own (G,O) pairs for the same units. Matvec code identical across
// roles (no divergence); activation uses per-lane constants; cell state
// duplicated on both role-lanes via a 2-shuffle exchange.

using u64 = unsigned long long;

__device__ __forceinline__ u64 fma2(u64 a, u64 b, u64 c) {
    u64 d;
    asm("fma.rn.f32x2 %0, %1, %2, %3;" : "=l"(d) : "l"(a), "l"(b), "l"(c));
    return d;
}
__device__ __forceinline__ u64 pk2(float lo, float hi) {
    u64 r;
    asm("mov.b64 %0, {%1, %2};" : "=l"(r) : "f"(lo), "f"(hi));
    return r;
}
__device__ __forceinline__ void up2(float& lo, float& hi, u64 v) {
    asm("mov.b64 {%0, %1}, %2;" : "=f"(lo), "=f"(hi) : "l"(v));
}
__device__ __forceinline__ float ex2_(float x) {
    float y; asm("ex2.approx.f32 %0, %1;" : "=f"(y) : "f"(x)); return y;
}
__device__ __forceinline__ float rcp_(float x) {
    float y; asm("rcp.approx.f32 %0, %1;" : "=f"(y) : "f"(x)); return y;
}

#define L2E 1.4426950408889634f

// row strides in u64 units; padded so the 8 simultaneous row addresses
// (r = jl + 5k, k=0..7) are distinct mod 16 u64 (128B) and 16B-aligned.
#define S0 22   // layer0 row: [pair 20][pad 2]            = 176 B
#define S1 42   // layer1 row: [u-pair 20][v-pair 20][pad 2] = 336 B

__global__ void __launch_bounds__(256, 1) lstm2_fc_kernel(
    const float* __restrict__ x,     // [B, T]
    const float* __restrict__ Wih0,  // [80, 1]
    const float* __restrict__ Whh0,  // [80, 20]
    const float* __restrict__ bih0,  // [80]
    const float* __restrict__ bhh0,  // [80]
    const float* __restrict__ Wih1,  // [80, 20]
    const float* __restrict__ Whh1,  // [80, 20]
    const float* __restrict__ bih1,  // [80]
    const float* __restrict__ bhh1,  // [80]
    const float* __restrict__ fcW,   // [1, 20]
    const float* __restrict__ fcb,   // [1]
    float* __restrict__ out,         // [B, 1]
    int Btot, int Tlen)
{
    // row id r = p*20 + j ; p=0 -> (I,F) = rows (j, 20+j); p=1 -> (G,O) = (40+j, 60+j)
    __shared__ __align__(16) u64 sm0[40 * S0];
    __shared__ __align__(16) u64 sm1[40 * S1];
    __shared__ __align__(16) u64 swx[40];
    __shared__ __align__(16) u64 sbb0[40];
    __shared__ __align__(16) u64 sbb1[40];
    __shared__ float sFc[20];
    __shared__ float sFcb;

    const int tid = threadIdx.x;

    for (int idx = tid; idx < 800; idx += 256) {
        int r = idx / 20, m = idx % 20;
        int p = r / 20, j = r % 20;
        int rlo = p ? (40 + j) : j;
        int rhi = rlo + 20;
        sm0[r * S0 + m] = pk2(Whh0[rlo * 20 + m], Whh0[rhi * 20 + m]);
    }
    for (int idx = tid; idx < 1600; idx += 256) {
        int r = idx / 40, t2 = idx % 40;
        int part = t2 / 20, m = t2 % 20;   // part 0 = u (Wih1), 1 = v (Whh1)
        int p = r / 20, j = r % 20;
        int rlo = p ? (40 + j) : j;
        int rhi = rlo + 20;
        const float* mat = part ? Whh1 : Wih1;
        sm1[r * S1 + part * 20 + m] = pk2(mat[rlo * 20 + m], mat[rhi * 20 + m]);
    }
    for (int r = tid; r < 40; r += 256) {
        int p = r / 20, j = r % 20;
        int rlo = p ? (40 + j) : j;
        int rhi = rlo + 20;
        swx[r]  = pk2(Wih0[rlo], Wih0[rhi]);
        sbb0[r] = pk2(bih0[rlo] + bhh0[rlo], bih0[rhi] + bhh0[rhi]);
        sbb1[r] = pk2(bih1[rlo] + bhh1[rlo], bih1[rhi] + bhh1[rhi]);
    }
    if (tid < 20) sFc[tid] = fcW[tid];
    if (tid == 0) sFcb = fcb[0];
    __syncthreads();

    // ---- lane mapping: 8 lanes per sequence ----
    const int grp = tid >> 3;            // 0..31 groups per block
    const int sub = tid & 7;             // role-lane
    const int p   = sub >> 2;            // 0 = IF, 1 = GO
    const int q   = sub & 3;             // unit slice
    const int jbase = q * 5;
    const bool isIF = (p == 0);

    int b = blockIdx.x * 32 + grp;
    const bool active = (b < Btot);
    if (b >= Btot) b = Btot - 1;
    const float* xb = x + (size_t)b * Tlen;

    // hoist per-lane x-weights & biases into registers
    u64 wx[5], b0r[5], b1r[5];
    #pragma unroll
    for (int jl = 0; jl < 5; ++jl) {
        int r = p * 20 + jbase + jl;
        wx[jl]  = swx[r];
        b0r[jl] = sbb0[r];
        b1r[jl] = sbb1[r];
    }

    // per-lane activation constants: lo-element act = kb2*sigm-core + kb3
    const float kk_lo = isIF ? -L2E : -2.0f * L2E;  // sigmoid vs tanh
    const float kb2   = isIF ? 1.0f : 2.0f;
    const float kb3   = isIF ? 0.0f : -1.0f;

    float c0[5], c1[5], h0s[5], h1s[5];
    #pragma unroll
    for (int i = 0; i < 5; ++i) { c0[i] = 0.f; c1[i] = 0.f; h0s[i] = 0.f; h1s[i] = 0.f; }

    u64 hh2[20], hb2[20];   // (h,h)-duplicated packed full vectors
    #pragma unroll
    for (int i = 0; i < 20; ++i) { hh2[i] = 0ull; hb2[i] = 0ull; }

    const unsigned FULL = 0xffffffffu;
    float xt_next = __ldg(&xb[0]);

    #pragma unroll 1
    for (int t = 0; t < Tlen; ++t) {
        const float xt = xt_next;
        if (t + 1 < Tlen) xt_next = __ldg(&xb[t + 1]);
        const u64 xt2 = pk2(xt, xt);

        // ---------------- layer 0 ----------------
        #pragma unroll
        for (int jl = 0; jl < 5; ++jl) {
            const u64* base = &sm0[(p * 20 + jbase + jl) * S0];
            u64 acc = fma2(wx[jl], xt2, b0r[jl]);
            #pragma unroll
            for (int mq = 0; mq < 10; ++mq) {
                ulonglong2 w = *reinterpret_cast<const ulonglong2*>(base + 2 * mq);
                acc = fma2(w.x, hh2[2 * mq],     acc);
                acc = fma2(w.y, hh2[2 * mq + 1], acc);
            }
            float lo, hi;
            up2(lo, hi, acc);
            float alo = fmaf(kb2, rcp_(1.0f + ex2_(kk_lo * lo)), kb3); // sigm(i) | tanh(g)
            float ahi = rcp_(1.0f + ex2_(-L2E * hi));                  // sigm(f) | sigm(o)
            float xlo = __shfl_xor_sync(FULL, alo, 4, 8);
            float xhi = __shfl_xor_sync(FULL, ahi, 4, 8);
            float gi = isIF ? alo : xlo;
            float gg = isIF ? xlo : alo;
            float gf = isIF ? ahi : xhi;
            float go = isIF ? xhi : ahi;
            float cn = fmaf(gf, c0[jl], gi * gg);
            c0[jl] = cn;
            float tcn = fmaf(2.0f, rcp_(1.0f + ex2_(-2.0f * L2E * cn)), -1.0f);
            h0s[jl] = go * tcn;
        }

        // gather full h0 (all 8 lanes need it)
        #pragma unroll
        for (int q2 = 0; q2 < 4; ++q2)
            #pragma unroll
            for (int mi = 0; mi < 5; ++mi) {
                float v = __shfl_sync(FULL, h0s[mi], q2, 8);
                hh2[q2 * 5 + mi] = pk2(v, v);
            }

        // ---------------- layer 1 ----------------
        #pragma unroll
        for (int jl = 0; jl < 5; ++jl) {
            const u64* base = &sm1[(p * 20 + jbase + jl) * S1];
            u64 acc = b1r[jl];
            #pragma unroll
            for (int mq = 0; mq < 10; ++mq) {
                ulonglong2 u = *reinterpret_cast<const ulonglong2*>(base + 2 * mq);       // u-pair
                ulonglong2 v = *reinterpret_cast<const ulonglong2*>(base + 20 + 2 * mq);  // v-pair (FIXED: +20)
                acc = fma2(u.x, hh2[2 * mq],     acc);
                acc = fma2(u.y, hh2[2 * mq + 1], acc);
                acc = fma2(v.x, hb2[2 * mq],     acc);
                acc = fma2(v.y, hb2[2 * mq + 1], acc);
            }
            float lo, hi;
            up2(lo, hi, acc);
            float alo = fmaf(kb2, rcp_(1.0f + ex2_(kk_lo * lo)), kb3);
            float ahi = rcp_(1.0f + ex2_(-L2E * hi));
            float xlo = __shfl_xor_sync(FULL, alo, 4, 8);
            float xhi = __shfl_xor_sync(FULL, ahi, 4, 8);
            float gi = isIF ? alo : xlo;
            float gg = isIF ? xlo : alo;
            float gf = isIF ? ahi : xhi;
            float go = isIF ? xhi : ahi;
            float cn = fmaf(gf, c1[jl], gi * gg);
            c1[jl] = cn;
            float tcn = fmaf(2.0f, rcp_(1.0f + ex2_(-2.0f * L2E * cn)), -1.0f);
            h1s[jl] = go * tcn;
        }

        // gather full h1 for next step
        #pragma unroll
        for (int q2 = 0; q2 < 4; ++q2)
            #pragma unroll
            for (int mi = 0; mi < 5; ++mi) {
                float v = __shfl_sync(FULL, h1s[mi], q2, 8);
                hb2[q2 * 5 + mi] = pk2(v, v);
            }
    }

    // FC head: both role-lanes hold identical h1s; reduce across q, write from sub==0
    float pr = 0.f;
    #pragma unroll
    for (int jl = 0; jl < 5; ++jl)
        pr = fmaf(sFc[jbase + jl], h1s[jl], pr);
    pr += __shfl_xor_sync(FULL, pr, 1, 8);
    pr += __shfl_xor_sync(FULL, pr, 2, 8);
    if (active && sub == 0)
        out[b] = pr + sFcb;
}

extern "C" void kernel_launch(void* const* d_in, const int* in_sizes, int n_in,
                              void* d_out, int out_size)
{
    const float* x    = (const float*)d_in[0];
    const float* Wih0 = (const float*)d_in[1];
    const float* Whh0 = (const float*)d_in[2];
    const float* bih0 = (const float*)d_in[3];
    const float* bhh0 = (const float*)d_in[4];
    const float* Wih1 = (const float*)d_in[5];
    const float* Whh1 = (const float*)d_in[6];
    const float* bih1 = (const float*)d_in[7];
    const float* bhh1 = (const float*)d_in[8];
    const float* fcW  = (const float*)d_in[9];
    const float* fcb  = (const float*)d_in[10];

    const int B = out_size;             // out is [B, 1] fp32
    const int T = in_sizes[0] / B;      // x is [B, T, 1]
    const int blocks = (B + 31) / 32;   // 32 sequences per 256-thread block

    lstm2_fc_kernel<<<blocks, 256>>>(x, Wih0, Whh0, bih0, bhh0,
                                     Wih1, Whh1, bih1, bhh1,
                                     fcW, fcb, (float*)d_out, B, T);
}

// round 6
// speedup vs baseline: 1.0278x; 1.0278x over previous
#include <cuda_runtime.h>
#include <cstddef>

// 2-layer LSTM (H=20) + FC head, B=4096, T=512, D=1.
// 8 lanes/seq, 2 sequences per thread (ILP), m-pair-packed weights & h,
// h exchanged through shared memory (no gather shuffles), role-split
// activations (lanes p=0: gates i,f ; p=1: gates g,o) as verified in R5.

using u64 = unsigned long long;

__device__ __forceinline__ u64 fma2(u64 a, u64 b, u64 c) {
    u64 d;
    asm("fma.rn.f32x2 %0, %1, %2, %3;" : "=l"(d) : "l"(a), "l"(b), "l"(c));
    return d;
}
__device__ __forceinline__ u64 pk2(float lo, float hi) {
    u64 r;
    asm("mov.b64 %0, {%1, %2};" : "=l"(r) : "f"(lo), "f"(hi));
    return r;
}
__device__ __forceinline__ void up2(float& lo, float& hi, u64 v) {
    asm("mov.b64 {%0, %1}, %2;" : "=f"(lo), "=f"(hi) : "l"(v));
}
__device__ __forceinline__ float ex2_(float x) {
    float y; asm("ex2.approx.f32 %0, %1;" : "=f"(y) : "f"(x)); return y;
}
__device__ __forceinline__ float rcp_(float x) {
    float y; asm("rcp.approx.f32 %0, %1;" : "=f"(y) : "f"(x)); return y;
}

#define L2E 1.4426950408889634f

// shared layouts (u64 units). lane8 = p*4+q.
// w0: [10 rowclass][8 lane][10 k]          stride 10 u64 = 80B  (banks conflict-free)
// w1: [10 rowclass][8 lane][22] (u:0-9, v:10-19, pad 2)  stride 22 u64 = 176B
#define W1S 22
// hsh (floats): [16 group][104]; inside group: seq*48 + layer*24 + j (20 used)
#define HGS 104
#define HSS 48
#define HLS 24

__global__ void __launch_bounds__(128, 1) lstm2_fc_kernel(
    const float* __restrict__ x,     // [B, T]
    const float* __restrict__ Wih0,  // [80, 1]
    const float* __restrict__ Whh0,  // [80, 20]
    const float* __restrict__ bih0,  // [80]
    const float* __restrict__ bhh0,  // [80]
    const float* __restrict__ Wih1,  // [80, 20]
    const float* __restrict__ Whh1,  // [80, 20]
    const float* __restrict__ bih1,  // [80]
    const float* __restrict__ bhh1,  // [80]
    const float* __restrict__ fcW,   // [1, 20]
    const float* __restrict__ fcb,   // [1]
    float* __restrict__ out,         // [B, 1]
    int Btot, int Tlen)
{
    __shared__ __align__(16) u64 w0[10 * 8 * 10];
    __shared__ __align__(16) u64 w1[10 * 8 * W1S];
    __shared__ float sb0[80], sb1[80], swx[80];
    __shared__ __align__(16) float hsh[16 * HGS];

    const int tid = threadIdx.x;

    // ---- fill packed weights ----
    for (int idx = tid; idx < 800; idx += 128) {
        int k = idx % 10, lane8 = (idx / 10) % 8, rr = idx / 80;
        int p = lane8 >> 2, q = lane8 & 3, gl = rr / 5, jl = rr % 5;
        int r = (p * 2 + gl) * 20 + q * 5 + jl;
        w0[(rr * 8 + lane8) * 10 + k] = pk2(Whh0[r * 20 + 2 * k], Whh0[r * 20 + 2 * k + 1]);
    }
    for (int idx = tid; idx < 1600; idx += 128) {
        int k = idx % 20, lane8 = (idx / 20) % 8, rr = idx / 160;
        int p = lane8 >> 2, q = lane8 & 3, gl = rr / 5, jl = rr % 5;
        int r = (p * 2 + gl) * 20 + q * 5 + jl;
        const float* mat = (k < 10) ? Wih1 : Whh1;
        int km = (k < 10) ? k : (k - 10);
        w1[(rr * 8 + lane8) * W1S + k] = pk2(mat[r * 20 + 2 * km], mat[r * 20 + 2 * km + 1]);
    }
    for (int r = tid; r < 80; r += 128) {
        sb0[r] = bih0[r] + bhh0[r];
        sb1[r] = bih1[r] + bhh1[r];
        swx[r] = Wih0[r];
    }
    __syncthreads();

    // ---- lane mapping ----
    const int g2  = tid >> 3;        // group 0..15 (2 seqs each)
    const int sub = tid & 7;
    const int p   = sub >> 2;        // 0: gates i,f ; 1: gates g,o
    const int q   = sub & 3;         // unit slice
    const int lane8 = sub;
    const bool isP1 = (p == 1);

    int sA = blockIdx.x * 32 + g2 * 2;
    int sB = sA + 1;
    const bool actA = (sA < Btot), actB = (sB < Btot);
    if (sA >= Btot) sA = Btot - 1;
    if (sB >= Btot) sB = Btot - 1;
    const float* xa = x + (size_t)sA * Tlen;
    const float* xb = x + (size_t)sB * Tlen;

    float* hg = &hsh[g2 * HGS];

    // per-lane row scalars: rows (gl,jl) -> r = (p*2+gl)*20 + q*5+jl
    float b0r[2][5], b1r[2][5], wxr[2][5];
    #pragma unroll
    for (int gl = 0; gl < 2; ++gl)
        #pragma unroll
        for (int jl = 0; jl < 5; ++jl) {
            int r = (p * 2 + gl) * 20 + q * 5 + jl;
            b0r[gl][jl] = sb0[r];
            b1r[gl][jl] = sb1[r];
            wxr[gl][jl] = swx[r];
        }

    // activation constants (lo-gate: sigmoid for p0(i), tanh for p1(g))
    const float kk0 = isP1 ? (-2.0f * L2E) : (-L2E);
    const float kb2 = isP1 ? 2.0f : 1.0f;
    const float kb3 = isP1 ? -1.0f : 0.0f;

    // state
    u64 hhA[10], hhB[10], hbA[10], hbB[10];   // m-packed h0 / h1
    float c0A[5], c0B[5], c1A[5], c1B[5];
    #pragma unroll
    for (int i = 0; i < 10; ++i) { hhA[i] = 0; hhB[i] = 0; hbA[i] = 0; hbB[i] = 0; }
    #pragma unroll
    for (int i = 0; i < 5; ++i) { c0A[i] = 0.f; c0B[i] = 0.f; c1A[i] = 0.f; c1B[i] = 0.f; }

    const unsigned FULL = 0xffffffffu;
    float xAn = __ldg(&xa[0]);
    float xBn = __ldg(&xb[0]);

    #pragma unroll 1
    for (int t = 0; t < Tlen; ++t) {
        const float xA = xAn, xB = xBn;
        if (t + 1 < Tlen) { xAn = __ldg(&xa[t + 1]); xBn = __ldg(&xb[t + 1]); }

        // ================= layer 0 =================
        #pragma unroll
        for (int jl = 0; jl < 5; ++jl) {
            u64 aA0, aB0, aA1, aB1;
            {   // gl = 0 and gl = 1 interleaved (4 independent chains x2 below)
                const u64* base0 = &w0[((0 * 5 + jl) * 8 + lane8) * 10];
                const u64* base1 = &w0[((1 * 5 + jl) * 8 + lane8) * 10];
                aA0 = pk2(fmaf(wxr[0][jl], xA, b0r[0][jl]), 0.f);
                aB0 = pk2(fmaf(wxr[0][jl], xB, b0r[0][jl]), 0.f);
                aA1 = pk2(fmaf(wxr[1][jl], xA, b0r[1][jl]), 0.f);
                aB1 = pk2(fmaf(wxr[1][jl], xB, b0r[1][jl]), 0.f);
                #pragma unroll
                for (int k = 0; k < 10; ++k) {
                    u64 w_0 = base0[k], w_1 = base1[k];
                    aA0 = fma2(w_0, hhA[k], aA0);
                    aB0 = fma2(w_0, hhB[k], aB0);
                    aA1 = fma2(w_1, hhA[k], aA1);
                    aB1 = fma2(w_1, hhB[k], aB1);
                }
            }
            float lA0, hA0, lB0, hB0, lA1, hA1, lB1, hB1;
            up2(lA0, hA0, aA0); up2(lB0, hB0, aB0);
            up2(lA1, hA1, aA1); up2(lB1, hB1, aB1);
            float gA0 = lA0 + hA0, gB0 = lB0 + hB0;   // gate gl0: i(p0)/g(p1)
            float gA1 = lA1 + hA1, gB1 = lB1 + hB1;   // gate gl1: f(p0)/o(p1)

            // activations
            float aA_0 = fmaf(kb2, rcp_(1.0f + ex2_(kk0 * gA0)), kb3);
            float aB_0 = fmaf(kb2, rcp_(1.0f + ex2_(kk0 * gB0)), kb3);
            float aA_1 = rcp_(1.0f + ex2_(-L2E * gA1));
            float aB_1 = rcp_(1.0f + ex2_(-L2E * gB1));
            // role exchange
            float xA_0 = __shfl_xor_sync(FULL, aA_0, 4, 8);
            float xB_0 = __shfl_xor_sync(FULL, aB_0, 4, 8);
            float xA_1 = __shfl_xor_sync(FULL, aA_1, 4, 8);
            float xB_1 = __shfl_xor_sync(FULL, aB_1, 4, 8);
            float giA = isP1 ? xA_0 : aA_0, ggA = isP1 ? aA_0 : xA_0;
            float gfA = isP1 ? xA_1 : aA_1, goA = isP1 ? aA_1 : xA_1;
            float giB = isP1 ? xB_0 : aB_0, ggB = isP1 ? aB_0 : xB_0;
            float gfB = isP1 ? xB_1 : aB_1, goB = isP1 ? aB_1 : xB_1;
            float cnA = fmaf(gfA, c0A[jl], giA * ggA);
            float cnB = fmaf(gfB, c0B[jl], giB * ggB);
            c0A[jl] = cnA; c0B[jl] = cnB;
            // tanh(cn): seq-split across role lanes, then exchange
            float tin = isP1 ? cnB : cnA;
            float tv  = fmaf(2.0f, rcp_(1.0f + ex2_(-2.0f * L2E * tin)), -1.0f);
            float txx = __shfl_xor_sync(FULL, tv, 4, 8);
            float tA  = isP1 ? txx : tv;
            float tB  = isP1 ? tv  : txx;
            float hA = goA * tA, hB = goB * tB;
            if (!isP1) {  // p0 lanes publish h0
                hg[0 * HSS + 0 * HLS + q * 5 + jl] = hA;
                hg[1 * HSS + 0 * HLS + q * 5 + jl] = hB;
            }
        }
        __syncwarp(FULL);
        #pragma unroll
        for (int k2 = 0; k2 < 5; ++k2) {  // load m-packed h0 (LDS.128 -> 2 u64)
            ulonglong2 vA = *reinterpret_cast<const ulonglong2*>(&hg[0 * HSS + 0 * HLS + 4 * k2]);
            ulonglong2 vB = *reinterpret_cast<const ulonglong2*>(&hg[1 * HSS + 0 * HLS + 4 * k2]);
            hhA[2 * k2] = vA.x; hhA[2 * k2 + 1] = vA.y;
            hhB[2 * k2] = vB.x; hhB[2 * k2 + 1] = vB.y;
        }

        // ================= layer 1 =================
        #pragma unroll
        for (int jl = 0; jl < 5; ++jl) {
            u64 aA0, aB0, aA1, aB1;
            {
                const u64* base0 = &w1[((0 * 5 + jl) * 8 + lane8) * W1S];
                const u64* base1 = &w1[((1 * 5 + jl) * 8 + lane8) * W1S];
                aA0 = pk2(b1r[0][jl], 0.f);
                aB0 = pk2(b1r[0][jl], 0.f);
                aA1 = pk2(b1r[1][jl], 0.f);
                aB1 = pk2(b1r[1][jl], 0.f);
                #pragma unroll
                for (int k = 0; k < 10; ++k) {
                    u64 u_0 = base0[k],      u_1 = base1[k];
                    u64 v_0 = base0[10 + k], v_1 = base1[10 + k];
                    aA0 = fma2(u_0, hhA[k], aA0);
                    aB0 = fma2(u_0, hhB[k], aB0);
                    aA1 = fma2(u_1, hhA[k], aA1);
                    aB1 = fma2(u_1, hhB[k], aB1);
                    aA0 = fma2(v_0, hbA[k], aA0);
                    aB0 = fma2(v_0, hbB[k], aB0);
                    aA1 = fma2(v_1, hbA[k], aA1);
                    aB1 = fma2(v_1, hbB[k], aB1);
                }
            }
            float lA0, hA0, lB0, hB0, lA1, hA1, lB1, hB1;
            up2(lA0, hA0, aA0); up2(lB0, hB0, aB0);
            up2(lA1, hA1, aA1); up2(lB1, hB1, aB1);
            float gA0 = lA0 + hA0, gB0 = lB0 + hB0;
            float gA1 = lA1 + hA1, gB1 = lB1 + hB1;

            float aA_0 = fmaf(kb2, rcp_(1.0f + ex2_(kk0 * gA0)), kb3);
            float aB_0 = fmaf(kb2, rcp_(1.0f + ex2_(kk0 * gB0)), kb3);
            float aA_1 = rcp_(1.0f + ex2_(-L2E * gA1));
            float aB_1 = rcp_(1.0f + ex2_(-L2E * gB1));
            float xA_0 = __shfl_xor_sync(FULL, aA_0, 4, 8);
            float xB_0 = __shfl_xor_sync(FULL, aB_0, 4, 8);
            float xA_1 = __shfl_xor_sync(FULL, aA_1, 4, 8);
            float xB_1 = __shfl_xor_sync(FULL, aB_1, 4, 8);
            float giA = isP1 ? xA_0 : aA_0, ggA = isP1 ? aA_0 : xA_0;
            float gfA = isP1 ? xA_1 : aA_1, goA = isP1 ? aA_1 : xA_1;
            float giB = isP1 ? xB_0 : aB_0, ggB = isP1 ? aB_0 : xB_0;
            float gfB = isP1 ? xB_1 : aB_1, goB = isP1 ? aB_1 : xB_1;
            float cnA = fmaf(gfA, c1A[jl], giA * ggA);
            float cnB = fmaf(gfB, c1B[jl], giB * ggB);
            c1A[jl] = cnA; c1B[jl] = cnB;
            float tin = isP1 ? cnB : cnA;
            float tv  = fmaf(2.0f, rcp_(1.0f + ex2_(-2.0f * L2E * tin)), -1.0f);
            float txx = __shfl_xor_sync(FULL, tv, 4, 8);
            float tA  = isP1 ? txx : tv;
            float tB  = isP1 ? tv  : txx;
            float hA = goA * tA, hB = goB * tB;
            if (!isP1) {  // publish h1
                hg[0 * HSS + 1 * HLS + q * 5 + jl] = hA;
                hg[1 * HSS + 1 * HLS + q * 5 + jl] = hB;
            }
        }
        __syncwarp(FULL);
        #pragma unroll
        for (int k2 = 0; k2 < 5; ++k2) {
            ulonglong2 vA = *reinterpret_cast<const ulonglong2*>(&hg[0 * HSS + 1 * HLS + 4 * k2]);
            ulonglong2 vB = *reinterpret_cast<const ulonglong2*>(&hg[1 * HSS + 1 * HLS + 4 * k2]);
            hbA[2 * k2] = vA.x; hbA[2 * k2 + 1] = vA.y;
            hbB[2 * k2] = vB.x; hbB[2 * k2 + 1] = vB.y;
        }
    }

    // ---- FC head: every lane holds full final h1 (hbA/hbB, m-packed) ----
    u64 accFA = 0ull, accFB = 0ull;
    #pragma unroll
    for (int k = 0; k < 10; ++k) {
        u64 f2 = pk2(__ldg(&fcW[2 * k]), __ldg(&fcW[2 * k + 1]));
        accFA = fma2(f2, hbA[k], accFA);
        accFB = fma2(f2, hbB[k], accFB);
    }
    float fl, fh;
    if (sub == 0) {
        float bias = __ldg(&fcb[0]);
        up2(fl, fh, accFA);
        if (actA) out[sA] = fl + fh + bias;
        up2(fl, fh, accFB);
        if (actB) out[sB] = fl + fh + bias;
    }
}

extern "C" void kernel_launch(void* const* d_in, const int* in_sizes, int n_in,
                              void* d_out, int out_size)
{
    const float* x    = (const float*)d_in[0];
    const float* Wih0 = (const float*)d_in[1];
    const float* Whh0 = (const float*)d_in[2];
    const float* bih0 = (const float*)d_in[3];
    const float* bhh0 = (const float*)d_in[4];
    const float* Wih1 = (const float*)d_in[5];
    const float* Whh1 = (const float*)d_in[6];
    const float* bih1 = (const float*)d_in[7];
    const float* bhh1 = (const float*)d_in[8];
    const float* fcW  = (const float*)d_in[9];
    const float* fcb  = (const float*)d_in[10];

    const int B = out_size;              // out is [B, 1] fp32
    const int T = in_sizes[0] / B;       // x is [B, T, 1]
    const int blocks = (B + 31) / 32;    // 32 seqs per 128-thread block

    lstm2_fc_kernel<<<blocks, 128>>>(x, Wih0, Whh0, bih0, bhh0,
                                     Wih1, Whh1, bih1, bhh1,
                                     fcW, fcb, (float*)d_out, B, T);
}